// round 1
// baseline (speedup 1.0000x reference)
#include <cuda_runtime.h>
#include <cuda_bf16.h>
#include <math.h>

// Problem constants
#define Bsz 4
#define Tsz 4096
#define Dsz 1024
#define Hsz 4
#define DKsz 256
#define DVsz 256
#define ROWS (Bsz*Tsz)        // 16384
#define STEPS 16

// -------- static device scratch (no allocations allowed) --------
__device__ float g_q[ROWS * Dsz];     // 64MB  q raw -> normalized q
__device__ float g_k[ROWS * Dsz];     // 64MB
__device__ float g_v[ROWS * Dsz];     // 64MB
__device__ float g_g[ROWS * Dsz];     // 64MB  gate projection
__device__ float g_o[ROWS * Dsz];     // 64MB  attention output
__device__ float g_beta[ROWS * Hsz];
__device__ float g_dec[ROWS * Hsz];

// ============================================================
// SGEMM: C[M,N] = A[M,K] @ B[K,N], fp32 row-major.
// 128x128 block tile, 256 threads, 8x8 per-thread microtile, BK=8.
// ============================================================
#define BM 128
#define BN 128
#define BK 8
#define TM 8
#define TN 8

__global__ __launch_bounds__(256) void sgemm_kernel(
    const float* __restrict__ A, const float* __restrict__ B,
    float* __restrict__ C, int M, int N, int K)
{
    __shared__ float As[BK][BM];
    __shared__ float Bs[BK][BN];

    const int bx = blockIdx.x;   // N tile
    const int by = blockIdx.y;   // M tile
    const int tid = threadIdx.x;
    const int tx = tid & 15;     // 0..15
    const int ty = tid >> 4;     // 0..15

    float acc[TM][TN];
#pragma unroll
    for (int i = 0; i < TM; i++)
#pragma unroll
        for (int j = 0; j < TN; j++) acc[i][j] = 0.f;

    const int a_row = tid >> 1;          // 0..127
    const int a_col = (tid & 1) * 4;     // 0 or 4
    const int b_row = tid >> 5;          // 0..7
    const int b_col = (tid & 31) * 4;    // 0..124

    const float* Ab = A + (size_t)(by * BM) * K;
    const float* Bb = B + bx * BN;

    for (int k0 = 0; k0 < K; k0 += BK) {
        float4 av = *(const float4*)(Ab + (size_t)a_row * K + k0 + a_col);
        As[a_col + 0][a_row] = av.x;
        As[a_col + 1][a_row] = av.y;
        As[a_col + 2][a_row] = av.z;
        As[a_col + 3][a_row] = av.w;
        float4 bv = *(const float4*)(Bb + (size_t)(k0 + b_row) * N + b_col);
        *(float4*)(&Bs[b_row][b_col]) = bv;
        __syncthreads();

#pragma unroll
        for (int k = 0; k < BK; k++) {
            float ar[TM], br[TN];
#pragma unroll
            for (int i = 0; i < TM; i++) ar[i] = As[k][ty * TM + i];
#pragma unroll
            for (int j = 0; j < TN; j++) br[j] = Bs[k][tx * TN + j];
#pragma unroll
            for (int i = 0; i < TM; i++)
#pragma unroll
                for (int j = 0; j < TN; j++) acc[i][j] += ar[i] * br[j];
        }
        __syncthreads();
    }

    float* Cb = C + (size_t)(by * BM + ty * TM) * N + bx * BN + tx * TN;
#pragma unroll
    for (int i = 0; i < TM; i++) {
#pragma unroll
        for (int j = 0; j < TN; j += 4) {
            *(float4*)(Cb + (size_t)i * N + j) =
                make_float4(acc[i][j], acc[i][j+1], acc[i][j+2], acc[i][j+3]);
        }
    }
}

// ============================================================
// beta / dec projections: one warp per row (b*T+t), 4 heads each.
// beta = sigmoid(x @ Wb); dec = exp(-exp(A_log)*softplus(x@Wa + dt_bias))
// ============================================================
__global__ __launch_bounds__(256) void beta_dec_kernel(
    const float* __restrict__ x, const float* __restrict__ Wb,
    const float* __restrict__ Wa, const float* __restrict__ A_log,
    const float* __restrict__ dt_bias,
    float* __restrict__ beta, float* __restrict__ dec)
{
    const int row = blockIdx.x * 8 + (threadIdx.x >> 5);
    const int lane = threadIdx.x & 31;
    if (row >= ROWS) return;

    float accb[4] = {0,0,0,0}, acca[4] = {0,0,0,0};
    const float* xr = x + (size_t)row * Dsz;
    const float4* Wb4 = (const float4*)Wb;   // [D][4] rows -> float4
    const float4* Wa4 = (const float4*)Wa;

    for (int i = lane; i < Dsz; i += 32) {
        float xv = xr[i];
        float4 wb = Wb4[i];
        float4 wa = Wa4[i];
        accb[0] += xv * wb.x; accb[1] += xv * wb.y;
        accb[2] += xv * wb.z; accb[3] += xv * wb.w;
        acca[0] += xv * wa.x; acca[1] += xv * wa.y;
        acca[2] += xv * wa.z; acca[3] += xv * wa.w;
    }
#pragma unroll
    for (int off = 16; off; off >>= 1) {
#pragma unroll
        for (int h = 0; h < 4; h++) {
            accb[h] += __shfl_xor_sync(0xffffffffu, accb[h], off);
            acca[h] += __shfl_xor_sync(0xffffffffu, acca[h], off);
        }
    }
    if (lane < 4) {
        int h = lane;
        float bv = 1.f / (1.f + expf(-accb[h]));
        float a = acca[h] + dt_bias[h];
        // stable softplus
        float sp = fmaxf(a, 0.f) + log1pf(expf(-fabsf(a)));
        float dv = expf(-expf(A_log[h]) * sp);
        beta[(size_t)row * Hsz + h] = bv;
        dec [(size_t)row * Hsz + h] = dv;
    }
}

// ============================================================
// L2-normalize q and k per (b,t,h) row of 256; q also scaled 1/sqrt(DK).
// One warp per row, 65536 rows.
// ============================================================
__global__ __launch_bounds__(256) void norm_qk_kernel(float* __restrict__ q,
                                                      float* __restrict__ k)
{
    const int row = blockIdx.x * 8 + (threadIdx.x >> 5); // 0..65535
    const int lane = threadIdx.x & 31;
    float4* qr = (float4*)(q + (size_t)row * DKsz);
    float4* kr = (float4*)(k + (size_t)row * DKsz);
    float4 q0 = qr[lane * 2], q1 = qr[lane * 2 + 1];
    float4 k0 = kr[lane * 2], k1 = kr[lane * 2 + 1];

    float sq = q0.x*q0.x + q0.y*q0.y + q0.z*q0.z + q0.w*q0.w
             + q1.x*q1.x + q1.y*q1.y + q1.z*q1.z + q1.w*q1.w;
    float sk = k0.x*k0.x + k0.y*k0.y + k0.z*k0.z + k0.w*k0.w
             + k1.x*k1.x + k1.y*k1.y + k1.z*k1.z + k1.w*k1.w;
#pragma unroll
    for (int off = 16; off; off >>= 1) {
        sq += __shfl_xor_sync(0xffffffffu, sq, off);
        sk += __shfl_xor_sync(0xffffffffu, sk, off);
    }
    float qs = rsqrtf(sq + 1e-6f) * 0.0625f;  // * DK^-0.5 (DK=256)
    float ks = rsqrtf(sk + 1e-6f);
    q0.x*=qs; q0.y*=qs; q0.z*=qs; q0.w*=qs;
    q1.x*=qs; q1.y*=qs; q1.z*=qs; q1.w*=qs;
    k0.x*=ks; k0.y*=ks; k0.z*=ks; k0.w*=ks;
    k1.x*=ks; k1.y*=ks; k1.z*=ks; k1.w*=ks;
    qr[lane * 2] = q0; qr[lane * 2 + 1] = q1;
    kr[lane * 2] = k0; kr[lane * 2 + 1] = k1;
}

// ============================================================
// Gated delta-rule recurrence.
// Column-parallel: state column j evolves independently:
//   s = dec*s; p = k.s; s += k * beta*(v_j - p); o_j = q.s
// One warp per column (8 state floats/lane, row = i*32+lane).
// CTA = 8 warps = 8 columns of one (b,h); k/q tiles of 16 steps in smem.
// ============================================================
__global__ __launch_bounds__(256) void recurrence_kernel(
    const float* __restrict__ q, const float* __restrict__ k,
    const float* __restrict__ v, const float* __restrict__ beta,
    const float* __restrict__ dec, float* __restrict__ o)
{
    const int cta = blockIdx.x;       // 512
    const int bh = cta >> 5;          // 0..15
    const int jg = cta & 31;          // column group
    const int b = bh >> 2, h = bh & 3;
    const int w = threadIdx.x >> 5, lane = threadIdx.x & 31;
    const int j = jg * 8 + w;

    __shared__ float sk[STEPS][DKsz];
    __shared__ float sq[STEPS][DKsz];
    __shared__ float sv[STEPS][8];
    __shared__ float sb[STEPS], sd[STEPS];

    float s[8];
#pragma unroll
    for (int i = 0; i < 8; i++) s[i] = 0.f;

    const size_t rowbase = (size_t)b * Tsz * Dsz + h * DKsz;

    for (int t0 = 0; t0 < Tsz; t0 += STEPS) {
        __syncthreads();
        // cooperative load of k/q tiles: 16 steps x 256 floats each
#pragma unroll
        for (int r = 0; r < 4; r++) {
            int idx = r * 256 + threadIdx.x;  // 0..1023 float4 slots
            int ss = idx >> 6;
            int d4 = (idx & 63) * 4;
            size_t gaddr = rowbase + (size_t)(t0 + ss) * Dsz + d4;
            *(float4*)&sk[ss][d4] = *(const float4*)(k + gaddr);
            *(float4*)&sq[ss][d4] = *(const float4*)(q + gaddr);
        }
        if (threadIdx.x < 128) {
            int ss = threadIdx.x >> 3, jj = threadIdx.x & 7;
            sv[ss][jj] = v[rowbase + (size_t)(t0 + ss) * Dsz + jg * 8 + jj];
        }
        if (threadIdx.x < STEPS) {
            size_t bidx = (size_t)(b * Tsz + t0 + threadIdx.x) * Hsz + h;
            sb[threadIdx.x] = beta[bidx];
            sd[threadIdx.x] = dec[bidx];
        }
        __syncthreads();

#pragma unroll 4
        for (int ss = 0; ss < STEPS; ss++) {
            const float de = sd[ss], be = sb[ss], vj = sv[ss][w];
            float kv[8];
            float p = 0.f;
#pragma unroll
            for (int i = 0; i < 8; i++) {
                kv[i] = sk[ss][i * 32 + lane];
                s[i] *= de;
                p += kv[i] * s[i];
            }
#pragma unroll
            for (int off = 16; off; off >>= 1)
                p += __shfl_xor_sync(0xffffffffu, p, off);
            const float u = be * (vj - p);
            float ov = 0.f;
#pragma unroll
            for (int i = 0; i < 8; i++) {
                s[i] += kv[i] * u;
                ov += sq[ss][i * 32 + lane] * s[i];
            }
#pragma unroll
            for (int off = 16; off; off >>= 1)
                ov += __shfl_xor_sync(0xffffffffu, ov, off);
            if (lane == 0)
                o[rowbase + (size_t)(t0 + ss) * Dsz + j] = ov;
        }
    }
}

// ============================================================
// Gated RMSNorm: o = o * rsqrt(mean(o^2)+1e-5) * norm_w * silu(gate)
// One warp per (b,t,h) row of 256. Writes gated result into `out`.
// ============================================================
__global__ __launch_bounds__(256) void gate_norm_kernel(
    const float* __restrict__ o, const float* __restrict__ g,
    const float* __restrict__ norm_w, float* __restrict__ out)
{
    const int row = blockIdx.x * 8 + (threadIdx.x >> 5); // 0..65535
    const int lane = threadIdx.x & 31;
    const float4* orow = (const float4*)(o + (size_t)row * DVsz);
    float4 o0 = orow[lane * 2], o1 = orow[lane * 2 + 1];

    float ss = o0.x*o0.x + o0.y*o0.y + o0.z*o0.z + o0.w*o0.w
             + o1.x*o1.x + o1.y*o1.y + o1.z*o1.z + o1.w*o1.w;
#pragma unroll
    for (int off = 16; off; off >>= 1)
        ss += __shfl_xor_sync(0xffffffffu, ss, off);
    float r = rsqrtf(ss * (1.f / 256.f) + 1e-5f);

    const float4* nw = (const float4*)norm_w;
    float4 w0 = nw[lane * 2], w1 = nw[lane * 2 + 1];
    const float4* grow = (const float4*)(g + (size_t)row * DVsz);
    float4 g0 = grow[lane * 2], g1 = grow[lane * 2 + 1];

    float4 r0, r1;
    r0.x = o0.x * r * w0.x * (g0.x / (1.f + expf(-g0.x)));
    r0.y = o0.y * r * w0.y * (g0.y / (1.f + expf(-g0.y)));
    r0.z = o0.z * r * w0.z * (g0.z / (1.f + expf(-g0.z)));
    r0.w = o0.w * r * w0.w * (g0.w / (1.f + expf(-g0.w)));
    r1.x = o1.x * r * w1.x * (g1.x / (1.f + expf(-g1.x)));
    r1.y = o1.y * r * w1.y * (g1.y / (1.f + expf(-g1.y)));
    r1.z = o1.z * r * w1.z * (g1.z / (1.f + expf(-g1.z)));
    r1.w = o1.w * r * w1.w * (g1.w / (1.f + expf(-g1.w)));

    float4* outr = (float4*)(out + (size_t)row * DVsz);
    outr[lane * 2] = r0;
    outr[lane * 2 + 1] = r1;
}

// ============================================================
// host launch
// ============================================================
extern "C" void kernel_launch(void* const* d_in, const int* in_sizes, int n_in,
                              void* d_out, int out_size)
{
    const float* x       = (const float*)d_in[0];
    const float* Wq      = (const float*)d_in[1];
    const float* Wk      = (const float*)d_in[2];
    const float* Wv      = (const float*)d_in[3];
    const float* Wb      = (const float*)d_in[4];
    const float* Wa      = (const float*)d_in[5];
    const float* A_log   = (const float*)d_in[6];
    const float* dt_bias = (const float*)d_in[7];
    const float* Wg      = (const float*)d_in[8];
    const float* norm_w  = (const float*)d_in[9];
    const float* Wo      = (const float*)d_in[10];
    float* out = (float*)d_out;

    float *q, *k, *v, *g, *o, *beta, *dec;
    cudaGetSymbolAddress((void**)&q, g_q);
    cudaGetSymbolAddress((void**)&k, g_k);
    cudaGetSymbolAddress((void**)&v, g_v);
    cudaGetSymbolAddress((void**)&g, g_g);
    cudaGetSymbolAddress((void**)&o, g_o);
    cudaGetSymbolAddress((void**)&beta, g_beta);
    cudaGetSymbolAddress((void**)&dec, g_dec);

    dim3 gemm_grid(Dsz / BN, ROWS / BM);  // (8, 128)
    sgemm_kernel<<<gemm_grid, 256>>>(x, Wq, q, ROWS, Dsz, Dsz);
    sgemm_kernel<<<gemm_grid, 256>>>(x, Wk, k, ROWS, Dsz, Dsz);
    sgemm_kernel<<<gemm_grid, 256>>>(x, Wv, v, ROWS, Dsz, Dsz);
    sgemm_kernel<<<gemm_grid, 256>>>(x, Wg, g, ROWS, Dsz, Dsz);

    beta_dec_kernel<<<ROWS / 8, 256>>>(x, Wb, Wa, A_log, dt_bias, beta, dec);
    norm_qk_kernel<<<(ROWS * Hsz) / 8, 256>>>(q, k);

    recurrence_kernel<<<Bsz * Hsz * 32, 256>>>(q, k, v, beta, dec, o);

    // gated rmsnorm writes into q buffer (free after recurrence)
    gate_norm_kernel<<<(ROWS * Hsz) / 8, 256>>>(o, g, norm_w, q);

    sgemm_kernel<<<gemm_grid, 256>>>(q, Wo, out, ROWS, Dsz, Dsz);
}

// round 3
// speedup vs baseline: 1.6383x; 1.6383x over previous
#include <cuda_runtime.h>
#include <cuda_bf16.h>
#include <math.h>
#include <cstdint>

// Problem constants
#define Bsz 4
#define Tsz 4096
#define Dsz 1024
#define Hsz 4
#define DKsz 256
#define DVsz 256
#define ROWS (Bsz*Tsz)        // 16384
#define STEPS 16

// -------- static device scratch (no allocations allowed) --------
__device__ float g_q[ROWS * Dsz];
__device__ float g_k[ROWS * Dsz];
__device__ float g_v[ROWS * Dsz];
__device__ float g_g[ROWS * Dsz];
__device__ float g_o[ROWS * Dsz];
__device__ float g_beta[ROWS * Hsz];
__device__ float g_dec[ROWS * Hsz];
// bf16 split operands
__device__ __nv_bfloat16 g_xh[ROWS * Dsz];
__device__ __nv_bfloat16 g_xl[ROWS * Dsz];
__device__ __nv_bfloat16 g_yh[ROWS * Dsz];
__device__ __nv_bfloat16 g_yl[ROWS * Dsz];
__device__ __nv_bfloat16 g_wth[5 * Dsz * Dsz];  // transposed weights hi
__device__ __nv_bfloat16 g_wtl[5 * Dsz * Dsz];  // transposed weights lo

// ============================================================
// helpers (baseline PTX only — no 'a'-suffix features)
// ============================================================
__device__ __forceinline__ uint32_t smem_to_u32(const void* p) {
    uint32_t a;
    asm("{ .reg .u64 t; cvta.to.shared.u64 t, %1; cvt.u32.u64 %0, t; }"
        : "=r"(a) : "l"(p));
    return a;
}
__device__ __forceinline__ void cp_async16(uint32_t s, const void* g) {
    asm volatile("cp.async.cg.shared.global [%0], [%1], 16;" :: "r"(s), "l"(g));
}
__device__ __forceinline__ void ldsm4(uint32_t& r0, uint32_t& r1, uint32_t& r2,
                                      uint32_t& r3, uint32_t addr) {
    asm volatile("ldmatrix.sync.aligned.m8n8.x4.shared.b16 {%0,%1,%2,%3}, [%4];"
                 : "=r"(r0), "=r"(r1), "=r"(r2), "=r"(r3) : "r"(addr));
}
__device__ __forceinline__ void mma16816(float* c, const uint32_t* a,
                                         uint32_t b0, uint32_t b1) {
    asm volatile(
        "mma.sync.aligned.m16n8k16.row.col.f32.bf16.bf16.f32 "
        "{%0,%1,%2,%3}, {%4,%5,%6,%7}, {%8,%9}, {%0,%1,%2,%3};"
        : "+f"(c[0]), "+f"(c[1]), "+f"(c[2]), "+f"(c[3])
        : "r"(a[0]), "r"(a[1]), "r"(a[2]), "r"(a[3]), "r"(b0), "r"(b1));
}

// ============================================================
// Preprocessing: fp32 -> (hi, lo) bf16 split
// ============================================================
__global__ __launch_bounds__(256) void split_kernel(
    const float* __restrict__ src, __nv_bfloat16* __restrict__ hi,
    __nv_bfloat16* __restrict__ lo)
{
    const int i = blockIdx.x * 256 + threadIdx.x;   // float4 index
    float4 v = ((const float4*)src)[i];
    __nv_bfloat16 h0 = __float2bfloat16(v.x), h1 = __float2bfloat16(v.y);
    __nv_bfloat16 h2 = __float2bfloat16(v.z), h3 = __float2bfloat16(v.w);
    __nv_bfloat16 l0 = __float2bfloat16(v.x - __bfloat162float(h0));
    __nv_bfloat16 l1 = __float2bfloat16(v.y - __bfloat162float(h1));
    __nv_bfloat16 l2 = __float2bfloat16(v.z - __bfloat162float(h2));
    __nv_bfloat16 l3 = __float2bfloat16(v.w - __bfloat162float(h3));
    ((__nv_bfloat162*)hi)[i*2]   = __halves2bfloat162(h0, h1);
    ((__nv_bfloat162*)hi)[i*2+1] = __halves2bfloat162(h2, h3);
    ((__nv_bfloat162*)lo)[i*2]   = __halves2bfloat162(l0, l1);
    ((__nv_bfloat162*)lo)[i*2+1] = __halves2bfloat162(l2, l3);
}

// ============================================================
// Preprocessing: transpose 1024x1024 fp32 weight, split into hi/lo bf16.
// ============================================================
__global__ __launch_bounds__(256) void transpose_split_kernel(
    const float* __restrict__ W, __nv_bfloat16* __restrict__ Th,
    __nv_bfloat16* __restrict__ Tl)
{
    __shared__ float tile[32][33];
    const int n0 = blockIdx.x * 32, k0 = blockIdx.y * 32;
    const int tx = threadIdx.x & 31, ty = threadIdx.x >> 5;
#pragma unroll
    for (int r = ty; r < 32; r += 8)
        tile[r][tx] = W[(size_t)(k0 + r) * Dsz + n0 + tx];
    __syncthreads();
#pragma unroll
    for (int r = ty; r < 32; r += 8) {
        float v = tile[tx][r];
        __nv_bfloat16 h = __float2bfloat16(v);
        __nv_bfloat16 l = __float2bfloat16(v - __bfloat162float(h));
        size_t o = (size_t)(n0 + r) * Dsz + k0 + tx;
        Th[o] = h;
        Tl[o] = l;
    }
}

// ============================================================
// bf16x3 GEMM via mma.sync (HMMA):
// C[16384,1024] = A @ B^T ; A [M,K] hi/lo bf16; Bt [N,K] hi/lo bf16; C fp32.
// CTA tile 128x128, BK=32, cp.async double buffer, 8 warps (4x2),
// warp tile 32(M)x64(N). D += Ah*Bh + Al*Bh + Ah*Bl.
// ============================================================
#define TILE_BYTES (128*80)          // one operand tile per stage: 10240 B
#define STAGE_BYTES (4*TILE_BYTES)   // Ah, Al, Bh, Bl: 40960 B
#define GEMM_SMEM (2*STAGE_BYTES)    // 81920 B

__global__ __launch_bounds__(256, 1) void gemm_mma_bf16x3(
    const __nv_bfloat16* __restrict__ Ah, const __nv_bfloat16* __restrict__ Al,
    const __nv_bfloat16* __restrict__ Bh, const __nv_bfloat16* __restrict__ Bl,
    float* __restrict__ C)
{
    extern __shared__ char sm[];
    const int tid = threadIdx.x;
    const int wid = tid >> 5, lane = tid & 31;
    const int bx = blockIdx.x, by = blockIdx.y;
    const int wm = wid & 3;          // warp row  (M: 4 x 32)
    const int wn = wid >> 2;         // warp col  (N: 2 x 64)

    const uint32_t sbase = smem_to_u32(sm);

    const __nv_bfloat16* srcs[4] = {
        Ah + (size_t)(by * 128) * Dsz,
        Al + (size_t)(by * 128) * Dsz,
        Bh + (size_t)(bx * 128) * Dsz,
        Bl + (size_t)(bx * 128) * Dsz
    };

    float acc[2][8][4];
#pragma unroll
    for (int mt = 0; mt < 2; mt++)
#pragma unroll
        for (int nt = 0; nt < 8; nt++)
#pragma unroll
            for (int i = 0; i < 4; i++) acc[mt][nt][i] = 0.f;

    // ---- stage loader: 4 tiles of 128 rows x 32 bf16 (64B), stride 80B ----
    auto load_stage = [&](int kc) {
        const uint32_t sdst = sbase + (kc & 1) * STAGE_BYTES;
        const int k0 = kc * 32;
#pragma unroll
        for (int t = 0; t < 4; t++) {
            const __nv_bfloat16* src = srcs[t];
#pragma unroll
            for (int i = 0; i < 2; i++) {
                int id = i * 256 + tid;         // 0..511
                int r = id >> 2, c = id & 3;
                cp_async16(sdst + t * TILE_BYTES + r * 80 + c * 16,
                           src + (size_t)r * Dsz + k0 + c * 8);
            }
        }
        asm volatile("cp.async.commit_group;" ::: "memory");
    };

    load_stage(0);

    // ldmatrix lane-address components (row = lane&15, col-half = lane>>4)
    const int lrow = lane & 15;
    const int lcolb = (lane >> 4) * 16;      // byte offset of 8-col half

    for (int kc = 0; kc < 32; kc++) {
        if (kc < 31) load_stage(kc + 1);
        else asm volatile("cp.async.commit_group;" ::: "memory");
        asm volatile("cp.async.wait_group 1;" ::: "memory");
        __syncthreads();

        const uint32_t s = sbase + (kc & 1) * STAGE_BYTES;
        const uint32_t sAh = s;
        const uint32_t sAl = s + TILE_BYTES;
        const uint32_t sBh = s + 2 * TILE_BYTES;
        const uint32_t sBl = s + 3 * TILE_BYTES;

#pragma unroll
        for (int ks = 0; ks < 2; ks++) {
            const uint32_t cb = ks * 32 + lcolb;   // k-step byte offset
            uint32_t ah[2][4], bh[4][4], al[2][4], bl[4][4];
#pragma unroll
            for (int mt = 0; mt < 2; mt++)
                ldsm4(ah[mt][0], ah[mt][1], ah[mt][2], ah[mt][3],
                      sAh + (wm * 32 + mt * 16 + lrow) * 80 + cb);
#pragma unroll
            for (int bt = 0; bt < 4; bt++)
                ldsm4(bh[bt][0], bh[bt][1], bh[bt][2], bh[bt][3],
                      sBh + (wn * 64 + bt * 16 + lrow) * 80 + cb);
            // Ah * Bh
#pragma unroll
            for (int mt = 0; mt < 2; mt++)
#pragma unroll
                for (int bt = 0; bt < 4; bt++) {
                    mma16816(acc[mt][bt*2],   ah[mt], bh[bt][0], bh[bt][2]);
                    mma16816(acc[mt][bt*2+1], ah[mt], bh[bt][1], bh[bt][3]);
                }
            // Al * Bh
#pragma unroll
            for (int mt = 0; mt < 2; mt++)
                ldsm4(al[mt][0], al[mt][1], al[mt][2], al[mt][3],
                      sAl + (wm * 32 + mt * 16 + lrow) * 80 + cb);
#pragma unroll
            for (int mt = 0; mt < 2; mt++)
#pragma unroll
                for (int bt = 0; bt < 4; bt++) {
                    mma16816(acc[mt][bt*2],   al[mt], bh[bt][0], bh[bt][2]);
                    mma16816(acc[mt][bt*2+1], al[mt], bh[bt][1], bh[bt][3]);
                }
            // Ah * Bl
#pragma unroll
            for (int bt = 0; bt < 4; bt++)
                ldsm4(bl[bt][0], bl[bt][1], bl[bt][2], bl[bt][3],
                      sBl + (wn * 64 + bt * 16 + lrow) * 80 + cb);
#pragma unroll
            for (int mt = 0; mt < 2; mt++)
#pragma unroll
                for (int bt = 0; bt < 4; bt++) {
                    mma16816(acc[mt][bt*2],   ah[mt], bl[bt][0], bl[bt][2]);
                    mma16816(acc[mt][bt*2+1], ah[mt], bl[bt][1], bl[bt][3]);
                }
        }
        __syncthreads();
    }

    // ---- epilogue: float2 stores straight to C ----
    const int crow = by * 128 + wm * 32 + (lane >> 2);
    const int ccol = bx * 128 + wn * 64 + (lane & 3) * 2;
#pragma unroll
    for (int mt = 0; mt < 2; mt++) {
#pragma unroll
        for (int nt = 0; nt < 8; nt++) {
            float* p0 = C + (size_t)(crow + mt * 16) * Dsz + ccol + nt * 8;
            float* p1 = p0 + 8 * Dsz;
            *(float2*)p0 = make_float2(acc[mt][nt][0], acc[mt][nt][1]);
            *(float2*)p1 = make_float2(acc[mt][nt][2], acc[mt][nt][3]);
        }
    }
}

// ============================================================
// beta / dec projections (unchanged)
// ============================================================
__global__ __launch_bounds__(256) void beta_dec_kernel(
    const float* __restrict__ x, const float* __restrict__ Wb,
    const float* __restrict__ Wa, const float* __restrict__ A_log,
    const float* __restrict__ dt_bias,
    float* __restrict__ beta, float* __restrict__ dec)
{
    const int row = blockIdx.x * 8 + (threadIdx.x >> 5);
    const int lane = threadIdx.x & 31;
    if (row >= ROWS) return;

    float accb[4] = {0,0,0,0}, acca[4] = {0,0,0,0};
    const float* xr = x + (size_t)row * Dsz;
    const float4* Wb4 = (const float4*)Wb;
    const float4* Wa4 = (const float4*)Wa;

    for (int i = lane; i < Dsz; i += 32) {
        float xv = xr[i];
        float4 wb = Wb4[i];
        float4 wa = Wa4[i];
        accb[0] += xv * wb.x; accb[1] += xv * wb.y;
        accb[2] += xv * wb.z; accb[3] += xv * wb.w;
        acca[0] += xv * wa.x; acca[1] += xv * wa.y;
        acca[2] += xv * wa.z; acca[3] += xv * wa.w;
    }
#pragma unroll
    for (int off = 16; off; off >>= 1) {
#pragma unroll
        for (int h = 0; h < 4; h++) {
            accb[h] += __shfl_xor_sync(0xffffffffu, accb[h], off);
            acca[h] += __shfl_xor_sync(0xffffffffu, acca[h], off);
        }
    }
    if (lane < 4) {
        int h = lane;
        float bv = 1.f / (1.f + expf(-accb[h]));
        float a = acca[h] + dt_bias[h];
        float sp = fmaxf(a, 0.f) + log1pf(expf(-fabsf(a)));
        float dv = expf(-expf(A_log[h]) * sp);
        beta[(size_t)row * Hsz + h] = bv;
        dec [(size_t)row * Hsz + h] = dv;
    }
}

// ============================================================
// L2-normalize q and k (unchanged)
// ============================================================
__global__ __launch_bounds__(256) void norm_qk_kernel(float* __restrict__ q,
                                                      float* __restrict__ k)
{
    const int row = blockIdx.x * 8 + (threadIdx.x >> 5);
    const int lane = threadIdx.x & 31;
    float4* qr = (float4*)(q + (size_t)row * DKsz);
    float4* kr = (float4*)(k + (size_t)row * DKsz);
    float4 q0 = qr[lane * 2], q1 = qr[lane * 2 + 1];
    float4 k0 = kr[lane * 2], k1 = kr[lane * 2 + 1];

    float sq = q0.x*q0.x + q0.y*q0.y + q0.z*q0.z + q0.w*q0.w
             + q1.x*q1.x + q1.y*q1.y + q1.z*q1.z + q1.w*q1.w;
    float sk = k0.x*k0.x + k0.y*k0.y + k0.z*k0.z + k0.w*k0.w
             + k1.x*k1.x + k1.y*k1.y + k1.z*k1.z + k1.w*k1.w;
#pragma unroll
    for (int off = 16; off; off >>= 1) {
        sq += __shfl_xor_sync(0xffffffffu, sq, off);
        sk += __shfl_xor_sync(0xffffffffu, sk, off);
    }
    float qs = rsqrtf(sq + 1e-6f) * 0.0625f;
    float ks = rsqrtf(sk + 1e-6f);
    q0.x*=qs; q0.y*=qs; q0.z*=qs; q0.w*=qs;
    q1.x*=qs; q1.y*=qs; q1.z*=qs; q1.w*=qs;
    k0.x*=ks; k0.y*=ks; k0.z*=ks; k0.w*=ks;
    k1.x*=ks; k1.y*=ks; k1.z*=ks; k1.w*=ks;
    qr[lane * 2] = q0; qr[lane * 2 + 1] = q1;
    kr[lane * 2] = k0; kr[lane * 2 + 1] = k1;
}

// ============================================================
// Gated delta-rule recurrence (unchanged)
// ============================================================
__global__ __launch_bounds__(256) void recurrence_kernel(
    const float* __restrict__ q, const float* __restrict__ k,
    const float* __restrict__ v, const float* __restrict__ beta,
    const float* __restrict__ dec, float* __restrict__ o)
{
    const int cta = blockIdx.x;
    const int bh = cta >> 5;
    const int jg = cta & 31;
    const int b = bh >> 2, h = bh & 3;
    const int w = threadIdx.x >> 5, lane = threadIdx.x & 31;
    const int j = jg * 8 + w;

    __shared__ float sk[STEPS][DKsz];
    __shared__ float sq[STEPS][DKsz];
    __shared__ float sv[STEPS][8];
    __shared__ float sb[STEPS], sd[STEPS];

    float s[8];
#pragma unroll
    for (int i = 0; i < 8; i++) s[i] = 0.f;

    const size_t rowbase = (size_t)b * Tsz * Dsz + h * DKsz;

    for (int t0 = 0; t0 < Tsz; t0 += STEPS) {
        __syncthreads();
#pragma unroll
        for (int r = 0; r < 4; r++) {
            int idx = r * 256 + threadIdx.x;
            int ss = idx >> 6;
            int d4 = (idx & 63) * 4;
            size_t gaddr = rowbase + (size_t)(t0 + ss) * Dsz + d4;
            *(float4*)&sk[ss][d4] = *(const float4*)(k + gaddr);
            *(float4*)&sq[ss][d4] = *(const float4*)(q + gaddr);
        }
        if (threadIdx.x < 128) {
            int ss = threadIdx.x >> 3, jj = threadIdx.x & 7;
            sv[ss][jj] = v[rowbase + (size_t)(t0 + ss) * Dsz + jg * 8 + jj];
        }
        if (threadIdx.x < STEPS) {
            size_t bidx = (size_t)(b * Tsz + t0 + threadIdx.x) * Hsz + h;
            sb[threadIdx.x] = beta[bidx];
            sd[threadIdx.x] = dec[bidx];
        }
        __syncthreads();

#pragma unroll 4
        for (int ss = 0; ss < STEPS; ss++) {
            const float de = sd[ss], be = sb[ss], vj = sv[ss][w];
            float kv[8];
            float p = 0.f;
#pragma unroll
            for (int i = 0; i < 8; i++) {
                kv[i] = sk[ss][i * 32 + lane];
                s[i] *= de;
                p += kv[i] * s[i];
            }
#pragma unroll
            for (int off = 16; off; off >>= 1)
                p += __shfl_xor_sync(0xffffffffu, p, off);
            const float u = be * (vj - p);
            float ov = 0.f;
#pragma unroll
            for (int i = 0; i < 8; i++) {
                s[i] += kv[i] * u;
                ov += sq[ss][i * 32 + lane] * s[i];
            }
#pragma unroll
            for (int off = 16; off; off >>= 1)
                ov += __shfl_xor_sync(0xffffffffu, ov, off);
            if (lane == 0)
                o[rowbase + (size_t)(t0 + ss) * Dsz + j] = ov;
        }
    }
}

// ============================================================
// Gated RMSNorm (unchanged)
// ============================================================
__global__ __launch_bounds__(256) void gate_norm_kernel(
    const float* __restrict__ o, const float* __restrict__ g,
    const float* __restrict__ norm_w, float* __restrict__ out)
{
    const int row = blockIdx.x * 8 + (threadIdx.x >> 5);
    const int lane = threadIdx.x & 31;
    const float4* orow = (const float4*)(o + (size_t)row * DVsz);
    float4 o0 = orow[lane * 2], o1 = orow[lane * 2 + 1];

    float ss = o0.x*o0.x + o0.y*o0.y + o0.z*o0.z + o0.w*o0.w
             + o1.x*o1.x + o1.y*o1.y + o1.z*o1.z + o1.w*o1.w;
#pragma unroll
    for (int off = 16; off; off >>= 1)
        ss += __shfl_xor_sync(0xffffffffu, ss, off);
    float r = rsqrtf(ss * (1.f / 256.f) + 1e-5f);

    const float4* nw = (const float4*)norm_w;
    float4 w0 = nw[lane * 2], w1 = nw[lane * 2 + 1];
    const float4* grow = (const float4*)(g + (size_t)row * DVsz);
    float4 g0 = grow[lane * 2], g1 = grow[lane * 2 + 1];

    float4 r0, r1;
    r0.x = o0.x * r * w0.x * (g0.x / (1.f + expf(-g0.x)));
    r0.y = o0.y * r * w0.y * (g0.y / (1.f + expf(-g0.y)));
    r0.z = o0.z * r * w0.z * (g0.z / (1.f + expf(-g0.z)));
    r0.w = o0.w * r * w0.w * (g0.w / (1.f + expf(-g0.w)));
    r1.x = o1.x * r * w1.x * (g1.x / (1.f + expf(-g1.x)));
    r1.y = o1.y * r * w1.y * (g1.y / (1.f + expf(-g1.y)));
    r1.z = o1.z * r * w1.z * (g1.z / (1.f + expf(-g1.z)));
    r1.w = o1.w * r * w1.w * (g1.w / (1.f + expf(-g1.w)));

    float4* outr = (float4*)(out + (size_t)row * DVsz);
    outr[lane * 2] = r0;
    outr[lane * 2 + 1] = r1;
}

// ============================================================
// host launch
// ============================================================
extern "C" void kernel_launch(void* const* d_in, const int* in_sizes, int n_in,
                              void* d_out, int out_size)
{
    const float* x       = (const float*)d_in[0];
    const float* Wq      = (const float*)d_in[1];
    const float* Wk      = (const float*)d_in[2];
    const float* Wv      = (const float*)d_in[3];
    const float* Wb      = (const float*)d_in[4];
    const float* Wa      = (const float*)d_in[5];
    const float* A_log   = (const float*)d_in[6];
    const float* dt_bias = (const float*)d_in[7];
    const float* Wg      = (const float*)d_in[8];
    const float* norm_w  = (const float*)d_in[9];
    const float* Wo      = (const float*)d_in[10];
    float* out = (float*)d_out;

    float *q, *k, *v, *g, *o, *beta, *dec;
    cudaGetSymbolAddress((void**)&q, g_q);
    cudaGetSymbolAddress((void**)&k, g_k);
    cudaGetSymbolAddress((void**)&v, g_v);
    cudaGetSymbolAddress((void**)&g, g_g);
    cudaGetSymbolAddress((void**)&o, g_o);
    cudaGetSymbolAddress((void**)&beta, g_beta);
    cudaGetSymbolAddress((void**)&dec, g_dec);
    __nv_bfloat16 *xh, *xl, *yh, *yl, *wth, *wtl;
    cudaGetSymbolAddress((void**)&xh, g_xh);
    cudaGetSymbolAddress((void**)&xl, g_xl);
    cudaGetSymbolAddress((void**)&yh, g_yh);
    cudaGetSymbolAddress((void**)&yl, g_yl);
    cudaGetSymbolAddress((void**)&wth, g_wth);
    cudaGetSymbolAddress((void**)&wtl, g_wtl);

    cudaFuncSetAttribute(gemm_mma_bf16x3,
                         cudaFuncAttributeMaxDynamicSharedMemorySize,
                         GEMM_SMEM);

    // --- preprocess: transpose+split weights, split x ---
    dim3 tgrid(Dsz / 32, Dsz / 32);
    transpose_split_kernel<<<tgrid, 256>>>(Wq, wth + 0*Dsz*Dsz, wtl + 0*Dsz*Dsz);
    transpose_split_kernel<<<tgrid, 256>>>(Wk, wth + 1*Dsz*Dsz, wtl + 1*Dsz*Dsz);
    transpose_split_kernel<<<tgrid, 256>>>(Wv, wth + 2*Dsz*Dsz, wtl + 2*Dsz*Dsz);
    transpose_split_kernel<<<tgrid, 256>>>(Wg, wth + 3*Dsz*Dsz, wtl + 3*Dsz*Dsz);
    transpose_split_kernel<<<tgrid, 256>>>(Wo, wth + 4*Dsz*Dsz, wtl + 4*Dsz*Dsz);
    split_kernel<<<(ROWS * Dsz / 4) / 256, 256>>>(x, xh, xl);

    // --- input projections via HMMA bf16x3 ---
    dim3 ggrid(Dsz / 128, ROWS / 128);  // (8, 128)
    gemm_mma_bf16x3<<<ggrid, 256, GEMM_SMEM>>>(xh, xl, wth + 0*Dsz*Dsz, wtl + 0*Dsz*Dsz, q);
    gemm_mma_bf16x3<<<ggrid, 256, GEMM_SMEM>>>(xh, xl, wth + 1*Dsz*Dsz, wtl + 1*Dsz*Dsz, k);
    gemm_mma_bf16x3<<<ggrid, 256, GEMM_SMEM>>>(xh, xl, wth + 2*Dsz*Dsz, wtl + 2*Dsz*Dsz, v);
    gemm_mma_bf16x3<<<ggrid, 256, GEMM_SMEM>>>(xh, xl, wth + 3*Dsz*Dsz, wtl + 3*Dsz*Dsz, g);

    beta_dec_kernel<<<ROWS / 8, 256>>>(x, Wb, Wa, A_log, dt_bias, beta, dec);
    norm_qk_kernel<<<(ROWS * Hsz) / 8, 256>>>(q, k);

    recurrence_kernel<<<Bsz * Hsz * 32, 256>>>(q, k, v, beta, dec, o);

    // gated rmsnorm -> q buffer (free), then split + output projection
    gate_norm_kernel<<<(ROWS * Hsz) / 8, 256>>>(o, g, norm_w, q);
    split_kernel<<<(ROWS * Dsz / 4) / 256, 256>>>(q, yh, yl);
    gemm_mma_bf16x3<<<ggrid, 256, GEMM_SMEM>>>(yh, yl, wth + 4*Dsz*Dsz, wtl + 4*Dsz*Dsz, out);
}